// round 3
// baseline (speedup 1.0000x reference)
#include <cuda_runtime.h>
#include <cuda_fp16.h>
#include <cstdint>

// Problem constants
#define MTOT   8192          // B*S
#define IN_CH  256
#define NEXP   8
#define NBASIS 13
#define KTOT   2048          // IN_CH * NEXP
#define NTOT   256           // OUT

__device__ __half g_Bm[(size_t)KTOT * NTOT];   // softmax gates, [k=i*8+e][o], fp16 (1 MB)

// ---------------------------------------------------------------------------
// Kernel 1: gates = softmax(gating_weights, axis=-1) -> G[k=i*8+e][o] fp16
// ---------------------------------------------------------------------------
__global__ void prep_G_kernel(const float* __restrict__ gw) {
    int t = blockIdx.x * 256 + threadIdx.x;       // t = i*256 + o
    int o = t & 255;
    int i = t >> 8;
    const float* g = gw + (size_t)t * NEXP;
    float v[NEXP];
    float mx = -1e30f;
#pragma unroll
    for (int e = 0; e < NEXP; e++) { v[e] = g[e]; mx = fmaxf(mx, v[e]); }
    float s = 0.f;
#pragma unroll
    for (int e = 0; e < NEXP; e++) { v[e] = __expf(v[e] - mx); s += v[e]; }
    float inv = 1.0f / s;
#pragma unroll
    for (int e = 0; e < NEXP; e++)
        g_Bm[(size_t)(i * NEXP + e) * NTOT + o] = __float2half(v[e] * inv);
}

// ---------------------------------------------------------------------------
// Fused kernel: out[m][o] = sum_k A[m][k] G[k][o], A computed on the fly from
// x via closed-form cubic B-spline + 8-expert combine (fp16 table, HFMA2).
// BM=128 BN=128 BK=32 (= 4 input channels per K-step), 8 warps (4x2, 32x64).
// ---------------------------------------------------------------------------
#define BM  128
#define BN  128
#define BK  32
#define AKP 40    // A smem row stride (halves)
#define BNP 136   // B smem row stride (halves): 272B -> word stride 68 = 4 mod 32

__device__ __forceinline__ uint32_t smem_addr(const void* p) {
    return (uint32_t)__cvta_generic_to_shared(p);
}

__device__ __forceinline__ void mma16816(float* d, const uint32_t* a,
                                         uint32_t b0, uint32_t b1) {
    asm volatile(
        "mma.sync.aligned.m16n8k16.row.col.f32.f16.f16.f32 "
        "{%0,%1,%2,%3}, {%4,%5,%6,%7}, {%8,%9}, {%0,%1,%2,%3};"
        : "+f"(d[0]), "+f"(d[1]), "+f"(d[2]), "+f"(d[3])
        : "r"(a[0]), "r"(a[1]), "r"(a[2]), "r"(a[3]), "r"(b0), "r"(b1));
}

// Compute 8 expert outputs (fp16 packed as uint4) for one x value.
// Ct: smem coeff table, 13 rows x 16B (4 half2 per row).
__device__ __forceinline__ uint4 eval8(float xv, const uint4* __restrict__ Ct) {
    xv = fminf(fmaxf(xv, -1.0f), 1.0f - 1e-6f);
    float u = (xv + 1.0f) * 5.0f;
    int i0 = (int)u;
    i0 = i0 > 9 ? 9 : (i0 < 0 ? 0 : i0);
    u -= (float)i0;
    float om = 1.0f - u;
    float u2 = u * u, u3 = u2 * u;
    float b0 = om * om * om * (1.0f / 6.0f);
    float b1 = (3.0f * u3 - 6.0f * u2 + 4.0f) * (1.0f / 6.0f);
    float b2 = (-3.0f * u3 + 3.0f * u2 + 3.0f * u + 1.0f) * (1.0f / 6.0f);
    float b3 = u3 * (1.0f / 6.0f);
    half2 w0 = __float2half2_rn(b0), w1 = __float2half2_rn(b1);
    half2 w2 = __float2half2_rn(b2), w3 = __float2half2_rn(b3);

    uint4 r0 = Ct[i0], r1 = Ct[i0 + 1], r2 = Ct[i0 + 2], r3 = Ct[i0 + 3];
    union { uint4 v; half2 h[4]; } c0, c1, c2, c3, out;
    c0.v = r0; c1.v = r1; c2.v = r2; c3.v = r3;
#pragma unroll
    for (int p = 0; p < 4; p++) {
        half2 a = __hmul2(w0, c0.h[p]);
        a = __hfma2(w1, c1.h[p], a);
        a = __hfma2(w2, c2.h[p], a);
        a = __hfma2(w3, c3.h[p], a);
        out.h[p] = a;
    }
    return out.v;
}

__global__ __launch_bounds__(256, 1)
void fused_kernel(const float* __restrict__ x,
                  const float* __restrict__ coeff,
                  float* __restrict__ C) {
    __shared__ __half As[2][BM * AKP];
    __shared__ __half Bs[2][BK * BNP];
    __shared__ uint4  Ct[NBASIS];        // 13 rows x 8 experts fp16 (16B rows)

    const int tid  = threadIdx.x;
    const int lane = tid & 31;
    const int warp = tid >> 5;
    const int wm = (warp & 3) * 32;
    const int wn = (warp >> 2) * 64;
    const int g  = lane >> 2;
    const int c2 = (lane & 3) * 2;

    const int m0 = blockIdx.x * BM;
    const int n0 = blockIdx.y * BN;

    // coeff table -> smem fp16
    if (tid < NBASIS * NEXP) {
        int e = tid & 7, n = tid >> 3;
        ((__half*)Ct)[n * 8 + e] = __float2half(coeff[e * NBASIS + n]);
    }

    // producer thread mapping
    const int er = warp * 16 + (lane & 7);   // eval rows er, er+8 (local)
    const int ec = lane >> 3;                // channel 0..3 within K-step
    const int bkr = tid & 31;                // B k-row within BK
    const int bco = (tid >> 5) * 16;         // B col (halves) within BN, 16 per thread

    float acc[2][8][4];
#pragma unroll
    for (int mi = 0; mi < 2; mi++)
#pragma unroll
        for (int jn = 0; jn < 8; jn++)
#pragma unroll
            for (int q = 0; q < 4; q++) acc[mi][jn][q] = 0.f;

    __syncthreads();   // coeff table ready

    // prologue: produce tile 0 -> buffer 0
    {
        float xa = x[(size_t)(m0 + er) * IN_CH + ec];
        float xb = x[(size_t)(m0 + er + 8) * IN_CH + ec];
        uint4 bv0 = *(const uint4*)&g_Bm[(size_t)bkr * NTOT + n0 + bco];
        uint4 bv1 = *(const uint4*)&g_Bm[(size_t)bkr * NTOT + n0 + bco + 8];
        *(uint4*)&As[0][er * AKP + ec * 8]       = eval8(xa, Ct);
        *(uint4*)&As[0][(er + 8) * AKP + ec * 8] = eval8(xb, Ct);
        *(uint4*)&Bs[0][bkr * BNP + bco]         = bv0;
        *(uint4*)&Bs[0][bkr * BNP + bco + 8]     = bv1;
    }
    __syncthreads();

    const int NK = KTOT / BK;  // 64
    for (int kt = 0; kt < NK; kt++) {
        const int cur = kt & 1;
        float xa, xb; uint4 bv0, bv1;
        if (kt + 1 < NK) {               // stage next-tile globals
            const int kb = (kt + 1) * 4; // channel base
            xa = x[(size_t)(m0 + er) * IN_CH + kb + ec];
            xb = x[(size_t)(m0 + er + 8) * IN_CH + kb + ec];
            const __half* bp = &g_Bm[(size_t)((kt + 1) * BK + bkr) * NTOT + n0 + bco];
            bv0 = *(const uint4*)bp;
            bv1 = *(const uint4*)(bp + 8);
        }

        const __half* Asb = As[cur];
        const __half* Bsb = Bs[cur];
#pragma unroll
        for (int s = 0; s < 2; s++) {
            uint32_t a[2][4];
#pragma unroll
            for (int mi = 0; mi < 2; mi++) {
                const __half* p = Asb + (wm + mi * 16 + g) * AKP + s * 16 + c2;
                a[mi][0] = *(const uint32_t*)p;
                a[mi][1] = *(const uint32_t*)(p + 8 * AKP);
                a[mi][2] = *(const uint32_t*)(p + 8);
                a[mi][3] = *(const uint32_t*)(p + 8 * AKP + 8);
            }
#pragma unroll
            for (int jn = 0; jn < 8; jn++) {
                uint32_t b0, b1;
                uint32_t ad = smem_addr(Bsb + (s * 16 + (lane & 15)) * BNP
                                            + wn + jn * 8);
                asm volatile(
                    "ldmatrix.sync.aligned.m8n8.x2.trans.shared.b16 {%0,%1}, [%2];"
                    : "=r"(b0), "=r"(b1) : "r"(ad));
#pragma unroll
                for (int mi = 0; mi < 2; mi++)
                    mma16816(acc[mi][jn], a[mi], b0, b1);
            }
        }

        if (kt + 1 < NK) {               // produce next tile into other buffer
            const int nxt = cur ^ 1;
            *(uint4*)&As[nxt][er * AKP + ec * 8]       = eval8(xa, Ct);
            *(uint4*)&As[nxt][(er + 8) * AKP + ec * 8] = eval8(xb, Ct);
            *(uint4*)&Bs[nxt][bkr * BNP + bco]         = bv0;
            *(uint4*)&Bs[nxt][bkr * BNP + bco + 8]     = bv1;
        }
        __syncthreads();
    }

    // epilogue
#pragma unroll
    for (int mi = 0; mi < 2; mi++) {
#pragma unroll
        for (int jn = 0; jn < 8; jn++) {
            int row = m0 + wm + mi * 16 + g;
            int col = n0 + wn + jn * 8 + c2;
            float2 v0 = make_float2(acc[mi][jn][0], acc[mi][jn][1]);
            float2 v1 = make_float2(acc[mi][jn][2], acc[mi][jn][3]);
            *(float2*)&C[(size_t)row * NTOT + col]       = v0;
            *(float2*)&C[(size_t)(row + 8) * NTOT + col] = v1;
        }
    }
}

// ---------------------------------------------------------------------------
extern "C" void kernel_launch(void* const* d_in, const int* in_sizes, int n_in,
                              void* d_out, int out_size) {
    (void)in_sizes; (void)n_in; (void)out_size;
    const float* x     = (const float*)d_in[0];   // (4,2048,256) f32
    const float* coeff = (const float*)d_in[1];   // (8,13) f32
    const float* gw    = (const float*)d_in[2];   // (256,256,8) f32
    float* out = (float*)d_out;                   // (4,2048,256) f32

    prep_G_kernel<<<256, 256>>>(gw);
    dim3 grid(MTOT / BM, NTOT / BN);
    fused_kernel<<<grid, 256>>>(x, coeff, out);
}

// round 5
// speedup vs baseline: 1.0649x; 1.0649x over previous
#include <cuda_runtime.h>
#include <cuda_fp16.h>
#include <cstdint>

// Problem constants
#define MTOT   8192          // B*S
#define IN_CH  256
#define NEXP   8
#define NBASIS 13
#define KTOT   2048          // IN_CH * NEXP
#define NTOT   256           // OUT

__device__ __half g_Bm[(size_t)KTOT * NTOT];   // softmax gates [k=i*8+e][o], fp16

// ---------------------------------------------------------------------------
// Kernel 1: gates = softmax(gating_weights, axis=-1) -> G[k][o]
// ---------------------------------------------------------------------------
__global__ void prep_G_kernel(const float* __restrict__ gw) {
    int t = blockIdx.x * 256 + threadIdx.x;       // t = i*256 + o
    int o = t & 255;
    int i = t >> 8;
    const float4* g4 = (const float4*)(gw + (size_t)t * NEXP);
    float4 va = g4[0], vb = g4[1];
    float v[NEXP] = {va.x, va.y, va.z, va.w, vb.x, vb.y, vb.z, vb.w};
    float mx = v[0];
#pragma unroll
    for (int e = 1; e < NEXP; e++) mx = fmaxf(mx, v[e]);
    float s = 0.f;
#pragma unroll
    for (int e = 0; e < NEXP; e++) { v[e] = __expf(v[e] - mx); s += v[e]; }
    float inv = 1.0f / s;
#pragma unroll
    for (int e = 0; e < NEXP; e++)
        g_Bm[(size_t)(i * NEXP + e) * NTOT + o] = __float2half(v[e] * inv);
}

// ---------------------------------------------------------------------------
// Fused kernel: C[m][o] = sum_k A[m][k] G[k][o], A produced on the fly.
// BM=128 BN=64 BK=64 (8 channels/step), 8 warps (4x2), 2 CTAs/SM.
// ---------------------------------------------------------------------------
#define BM  128
#define BN  64
#define BK  64
#define AKP 72    // A smem row stride (halves): 36 words == 4 mod 32
#define BNP 72    // B smem row stride (halves)

#define OFF_CT 0
#define OFF_A  256
#define ABUF   (BM * AKP * 2)            // 18432 B
#define OFF_B  (OFF_A + 2 * ABUF)
#define BBUF   (BK * BNP * 2)            // 9216 B
#define SMEM_NEED (OFF_B + 2 * BBUF)     // 55552 B

__device__ __forceinline__ uint32_t smem_addr(const void* p) {
    return (uint32_t)__cvta_generic_to_shared(p);
}

__device__ __forceinline__ void mma16816(float* d, const uint32_t* a,
                                         uint32_t b0, uint32_t b1) {
    asm volatile(
        "mma.sync.aligned.m16n8k16.row.col.f32.f16.f16.f32 "
        "{%0,%1,%2,%3}, {%4,%5,%6,%7}, {%8,%9}, {%0,%1,%2,%3};"
        : "+f"(d[0]), "+f"(d[1]), "+f"(d[2]), "+f"(d[3])
        : "r"(a[0]), "r"(a[1]), "r"(a[2]), "r"(a[3]), "r"(b0), "r"(b1));
}

__device__ __forceinline__ void ldm_x4(uint32_t* r, uint32_t ad) {
    asm volatile("ldmatrix.sync.aligned.m8n8.x4.shared.b16 {%0,%1,%2,%3}, [%4];"
                 : "=r"(r[0]), "=r"(r[1]), "=r"(r[2]), "=r"(r[3]) : "r"(ad));
}
__device__ __forceinline__ void ldm_x4t(uint32_t* r, uint32_t ad) {
    asm volatile("ldmatrix.sync.aligned.m8n8.x4.trans.shared.b16 {%0,%1,%2,%3}, [%4];"
                 : "=r"(r[0]), "=r"(r[1]), "=r"(r[2]), "=r"(r[3]) : "r"(ad));
}

// Cubic B-spline + 8-expert combine -> 8 fp16 (uint4). Ct: 13 x 16B rows.
__device__ __forceinline__ uint4 eval8(float xv, const uint4* __restrict__ Ct) {
    xv = fminf(fmaxf(xv, -1.0f), 1.0f - 1e-6f);
    float u = (xv + 1.0f) * 5.0f;
    int i0 = (int)u;
    i0 = i0 > 9 ? 9 : (i0 < 0 ? 0 : i0);
    u -= (float)i0;
    float om = 1.0f - u;
    float u2 = u * u, u3 = u2 * u;
    float b0 = om * om * om * (1.0f / 6.0f);
    float b1 = (3.0f * u3 - 6.0f * u2 + 4.0f) * (1.0f / 6.0f);
    float b2 = (-3.0f * u3 + 3.0f * u2 + 3.0f * u + 1.0f) * (1.0f / 6.0f);
    float b3 = u3 * (1.0f / 6.0f);
    half2 w0 = __float2half2_rn(b0), w1 = __float2half2_rn(b1);
    half2 w2 = __float2half2_rn(b2), w3 = __float2half2_rn(b3);
    union { uint4 v; half2 h[4]; } c0, c1, c2, c3, out;
    c0.v = Ct[i0]; c1.v = Ct[i0 + 1]; c2.v = Ct[i0 + 2]; c3.v = Ct[i0 + 3];
#pragma unroll
    for (int p = 0; p < 4; p++) {
        half2 a = __hmul2(w0, c0.h[p]);
        a = __hfma2(w1, c1.h[p], a);
        a = __hfma2(w2, c2.h[p], a);
        out.h[p] = __hfma2(w3, c3.h[p], a);
    }
    return out.v;
}

__global__ void __launch_bounds__(256, 2)
fused_kernel(const float* __restrict__ x,
             const float* __restrict__ coeff,
             float* __restrict__ C) {
    extern __shared__ char S[];
    uint4*  Ct = (uint4*)(S + OFF_CT);
    __half* As = (__half*)(S + OFF_A);
    __half* Bs = (__half*)(S + OFF_B);

    const int tid  = threadIdx.x;
    const int lane = tid & 31;
    const int warp = tid >> 5;
    const int wm = (warp & 3) * 32;
    const int wn = (warp >> 2) * 32;
    const int g  = lane >> 2;
    const int c2 = (lane & 3) * 2;

    const int m0 = blockIdx.x * BM;
    const int n0 = blockIdx.y * BN;

    if (tid < NBASIS * NEXP) {
        int e = tid & 7, n = tid >> 3;
        ((__half*)Ct)[n * 8 + e] = __float2half(coeff[e * NBASIS + n]);
    }

    // producer mapping: A — thread -> (row r, half hp): 4 channels each
    const int r  = tid >> 1;
    const int hp = tid & 1;
    const float* xrow = x + (size_t)(m0 + r) * IN_CH + hp * 4;
    // B: 64 rows x 64 cols per step; thread -> (bkr, 2x uint4)
    const int bkr = tid >> 2;
    const int bco = (tid & 3) * 16;
    const __half* Bg = g_Bm + n0 + bco;

    // consumer ldmatrix addresses (per-thread constants)
    const int a_row = lane & 15;
    const int a_co  = (lane >> 4) * 8;
    const int b_row = lane & 15;
    const int b_co  = (lane >> 4) * 8;

    float acc[2][4][4];
#pragma unroll
    for (int mi = 0; mi < 2; mi++)
#pragma unroll
        for (int jn = 0; jn < 4; jn++)
#pragma unroll
            for (int q = 0; q < 4; q++) acc[mi][jn][q] = 0.f;

    __syncthreads();   // coeff table ready

    // prologue: produce tile 0 -> buffer 0
    {
        float4 xv = *(const float4*)xrow;
        const __half* bp = Bg + (size_t)bkr * NTOT;
        uint4 bv0 = *(const uint4*)bp;
        uint4 bv1 = *(const uint4*)(bp + 8);
        __half* Ab = As + r * AKP + hp * 32;
        *(uint4*)(Ab + 0)  = eval8(xv.x, Ct);
        *(uint4*)(Ab + 8)  = eval8(xv.y, Ct);
        *(uint4*)(Ab + 16) = eval8(xv.z, Ct);
        *(uint4*)(Ab + 24) = eval8(xv.w, Ct);
        *(uint4*)(Bs + bkr * BNP + bco)     = bv0;
        *(uint4*)(Bs + bkr * BNP + bco + 8) = bv1;
    }
    __syncthreads();

    const int NK = KTOT / BK;  // 32
    for (int kt = 0; kt < NK; kt++) {
        const int cur = kt & 1;
        float4 xv; uint4 bv0, bv1;
        if (kt + 1 < NK) {
            xv = *(const float4*)(xrow + (kt + 1) * 8);
            const __half* bp = Bg + (size_t)((kt + 1) * BK + bkr) * NTOT;
            bv0 = *(const uint4*)bp;
            bv1 = *(const uint4*)(bp + 8);
        }

        const __half* Asb = As + cur * (BM * AKP);
        const __half* Bsb = Bs + cur * (BK * BNP);
#pragma unroll
        for (int s = 0; s < 4; s++) {      // four k16 steps per BK=64
            uint32_t af[2][4], bf[2][4];
#pragma unroll
            for (int mi = 0; mi < 2; mi++)
                ldm_x4(af[mi], smem_addr(Asb + (wm + mi * 16 + a_row) * AKP
                                             + s * 16 + a_co));
#pragma unroll
            for (int j2 = 0; j2 < 2; j2++)
                ldm_x4t(bf[j2], smem_addr(Bsb + (s * 16 + b_row) * BNP
                                              + wn + j2 * 16 + b_co));
#pragma unroll
            for (int mi = 0; mi < 2; mi++)
#pragma unroll
                for (int j2 = 0; j2 < 2; j2++) {
                    mma16816(acc[mi][j2 * 2 + 0], af[mi], bf[j2][0], bf[j2][1]);
                    mma16816(acc[mi][j2 * 2 + 1], af[mi], bf[j2][2], bf[j2][3]);
                }
        }

        if (kt + 1 < NK) {
            const int nxt = cur ^ 1;
            __half* Ab = As + nxt * (BM * AKP) + r * AKP + hp * 32;
            *(uint4*)(Ab + 0)  = eval8(xv.x, Ct);
            *(uint4*)(Ab + 8)  = eval8(xv.y, Ct);
            *(uint4*)(Ab + 16) = eval8(xv.z, Ct);
            *(uint4*)(Ab + 24) = eval8(xv.w, Ct);
            __half* Bb = Bs + nxt * (BK * BNP) + bkr * BNP + bco;
            *(uint4*)Bb       = bv0;
            *(uint4*)(Bb + 8) = bv1;
        }
        __syncthreads();
    }

    // epilogue
#pragma unroll
    for (int mi = 0; mi < 2; mi++) {
#pragma unroll
        for (int jn = 0; jn < 4; jn++) {
            int row = m0 + wm + mi * 16 + g;
            int col = n0 + wn + jn * 8 + c2;
            float2 v0 = make_float2(acc[mi][jn][0], acc[mi][jn][1]);
            float2 v1 = make_float2(acc[mi][jn][2], acc[mi][jn][3]);
            *(float2*)&C[(size_t)row * NTOT + col]       = v0;
            *(float2*)&C[(size_t)(row + 8) * NTOT + col] = v1;
        }
    }
}

// ---------------------------------------------------------------------------
extern "C" void kernel_launch(void* const* d_in, const int* in_sizes, int n_in,
                              void* d_out, int out_size) {
    (void)in_sizes; (void)n_in; (void)out_size;
    const float* x     = (const float*)d_in[0];   // (4,2048,256) f32
    const float* coeff = (const float*)d_in[1];   // (8,13) f32
    const float* gw    = (const float*)d_in[2];   // (256,256,8) f32
    float* out = (float*)d_out;                   // (4,2048,256) f32

    cudaFuncSetAttribute(fused_kernel,
                         cudaFuncAttributeMaxDynamicSharedMemorySize, SMEM_NEED);

    prep_G_kernel<<<256, 256>>>(gw);
    dim3 grid(MTOT / BM, NTOT / BN);
    fused_kernel<<<grid, 256, SMEM_NEED>>>(x, coeff, out);
}

// round 6
// speedup vs baseline: 1.1308x; 1.0619x over previous
#include <cuda_runtime.h>
#include <cuda_fp16.h>
#include <cstdint>

// Problem constants
#define MTOT   8192          // B*S
#define IN_CH  256
#define NEXP   8
#define NBASIS 13
#define KTOT   2048          // IN_CH * NEXP
#define NTOT   256           // OUT

// Scratch
__device__ float  g_xT[(size_t)IN_CH * MTOT];        // x transposed [ch][m], 8 MB
__device__ __half g_GB[(size_t)KTOT * NTOT];         // gates, blocked:
// layout: [nblk(4)][kt(32)][kl(64)][nl(64)]  (each [kl][nl] tile = contiguous 8KB)

// ---------------------------------------------------------------------------
// Prologue kernel: blocks 0..255 -> softmax gates (blocked layout);
//                  blocks 256..2303 -> transpose x into g_xT.
// ---------------------------------------------------------------------------
__global__ void prep_kernel(const float* __restrict__ gw,
                            const float* __restrict__ x) {
    if (blockIdx.x < 256) {
        int t = blockIdx.x * 256 + threadIdx.x;   // t = i*256 + o
        int o = t & 255;
        int i = t >> 8;
        const float4* g4 = (const float4*)(gw + (size_t)t * NEXP);
        float4 va = g4[0], vb = g4[1];
        float v[NEXP] = {va.x, va.y, va.z, va.w, vb.x, vb.y, vb.z, vb.w};
        float mx = v[0];
#pragma unroll
        for (int e = 1; e < NEXP; e++) mx = fmaxf(mx, v[e]);
        float s = 0.f;
#pragma unroll
        for (int e = 0; e < NEXP; e++) { v[e] = __expf(v[e] - mx); s += v[e]; }
        float inv = 1.0f / s;
        int nblk = o >> 6, nl = o & 63;
#pragma unroll
        for (int e = 0; e < NEXP; e++) {
            int k = i * NEXP + e;
            int kt = k >> 6, kl = k & 63;
            g_GB[(size_t)(((nblk * 32 + kt) * 64 + kl)) * 64 + nl] =
                __float2half(v[e] * inv);
        }
    } else {
        // transpose: 2048 tiles of 32m x 32ch
        __shared__ float T[32][33];
        int tb = blockIdx.x - 256;
        int tm = tb & 255;            // m-tile 0..255
        int tc = tb >> 8;             // ch-tile 0..7
        int m0 = tm * 32, c0 = tc * 32;
        int tx = threadIdx.x & 31, ty = threadIdx.x >> 5;   // (32, 8)
#pragma unroll
        for (int j = 0; j < 4; j++)
            T[ty + 8 * j][tx] = x[(size_t)(m0 + ty + 8 * j) * IN_CH + c0 + tx];
        __syncthreads();
#pragma unroll
        for (int j = 0; j < 4; j++)
            g_xT[(size_t)(c0 + ty + 8 * j) * MTOT + m0 + tx] = T[tx][ty + 8 * j];
    }
}

// ---------------------------------------------------------------------------
// Fused GEMM: C[m][o] = sum_k A[m][k] G[k][o], A produced on the fly.
// BM=128 BN=64 BK=64, 8 warps (4x2), 2 CTAs/SM. Coalesced loads + cp.async B.
// ---------------------------------------------------------------------------
#define BM  128
#define BN  64
#define BK  64
#define AKP 72    // A smem row stride (halves)
#define BNP 72    // B smem row stride (halves)

#define OFF_CT 0
#define OFF_A  256
#define ABUF   (BM * AKP * 2)            // 18432 B
#define OFF_B  (OFF_A + 2 * ABUF)
#define BBUF   (BK * BNP * 2)            // 9216 B
#define SMEM_NEED (OFF_B + 2 * BBUF)     // 55552 B

__device__ __forceinline__ uint32_t smem_addr(const void* p) {
    return (uint32_t)__cvta_generic_to_shared(p);
}

#define CP_ASYNC16(dst, src) \
    asm volatile("cp.async.cg.shared.global [%0], [%1], 16;" \
                 :: "r"(dst), "l"(src))
#define CP_COMMIT() asm volatile("cp.async.commit_group;")
#define CP_WAIT0()  asm volatile("cp.async.wait_group 0;" ::: "memory")

__device__ __forceinline__ void mma16816(float* d, const uint32_t* a,
                                         uint32_t b0, uint32_t b1) {
    asm volatile(
        "mma.sync.aligned.m16n8k16.row.col.f32.f16.f16.f32 "
        "{%0,%1,%2,%3}, {%4,%5,%6,%7}, {%8,%9}, {%0,%1,%2,%3};"
        : "+f"(d[0]), "+f"(d[1]), "+f"(d[2]), "+f"(d[3])
        : "r"(a[0]), "r"(a[1]), "r"(a[2]), "r"(a[3]), "r"(b0), "r"(b1));
}

__device__ __forceinline__ void ldm_x4(uint32_t* r, uint32_t ad) {
    asm volatile("ldmatrix.sync.aligned.m8n8.x4.shared.b16 {%0,%1,%2,%3}, [%4];"
                 : "=r"(r[0]), "=r"(r[1]), "=r"(r[2]), "=r"(r[3]) : "r"(ad));
}
__device__ __forceinline__ void ldm_x4t(uint32_t* r, uint32_t ad) {
    asm volatile("ldmatrix.sync.aligned.m8n8.x4.trans.shared.b16 {%0,%1,%2,%3}, [%4];"
                 : "=r"(r[0]), "=r"(r[1]), "=r"(r[2]), "=r"(r[3]) : "r"(ad));
}

// Cubic B-spline + 8-expert combine -> 8 fp16 (uint4). Ct: 13 x 16B rows.
__device__ __forceinline__ uint4 eval8(float xv, const uint4* __restrict__ Ct) {
    xv = fminf(fmaxf(xv, -1.0f), 1.0f - 1e-6f);
    float u = (xv + 1.0f) * 5.0f;
    int i0 = (int)u;
    i0 = i0 > 9 ? 9 : (i0 < 0 ? 0 : i0);
    u -= (float)i0;
    float om = 1.0f - u;
    float u2 = u * u, u3 = u2 * u;
    float b0 = om * om * om * (1.0f / 6.0f);
    float b1 = (3.0f * u3 - 6.0f * u2 + 4.0f) * (1.0f / 6.0f);
    float b2 = (-3.0f * u3 + 3.0f * u2 + 3.0f * u + 1.0f) * (1.0f / 6.0f);
    float b3 = u3 * (1.0f / 6.0f);
    half2 w0 = __float2half2_rn(b0), w1 = __float2half2_rn(b1);
    half2 w2 = __float2half2_rn(b2), w3 = __float2half2_rn(b3);
    union { uint4 v; half2 h[4]; } c0, c1, c2, c3, out;
    c0.v = Ct[i0]; c1.v = Ct[i0 + 1]; c2.v = Ct[i0 + 2]; c3.v = Ct[i0 + 3];
#pragma unroll
    for (int p = 0; p < 4; p++) {
        half2 a = __hmul2(w0, c0.h[p]);
        a = __hfma2(w1, c1.h[p], a);
        a = __hfma2(w2, c2.h[p], a);
        out.h[p] = __hfma2(w3, c3.h[p], a);
    }
    return out.v;
}

__global__ void __launch_bounds__(256, 2)
fused_kernel(const float* __restrict__ coeff, float* __restrict__ C) {
    extern __shared__ char S[];
    uint4*  Ct = (uint4*)(S + OFF_CT);
    __half* As = (__half*)(S + OFF_A);
    __half* Bs = (__half*)(S + OFF_B);

    const int tid  = threadIdx.x;
    const int lane = tid & 31;
    const int warp = tid >> 5;
    const int wm = (warp & 3) * 32;
    const int wn = (warp >> 2) * 32;
    const int g  = lane >> 2;
    const int c2 = (lane & 3) * 2;

    const int m0 = blockIdx.x * BM;
    const int n0 = blockIdx.y * BN;

    if (tid < NBASIS * NEXP) {
        int e = tid & 7, n = tid >> 3;
        ((__half*)Ct)[n * 8 + e] = __float2half(coeff[e * NBASIS + n]);
    }

    // producer A mapping: warp = channel (0..7 within chunk), lane = row base
    const int chw = warp;                 // channel within BK/8
    const int r32 = lane;                 // row base; rows r32 + 32j, j=0..3
    const float* xcol = g_xT + (size_t)chw * MTOT + m0 + r32;  // + kt*8*MTOT

    // producer B mapping (cp.async): thread t copies chunks 2t, 2t+1 (16B each)
    const int bc0 = 2 * tid;
    const __half* Bg = g_GB + (size_t)(n0 >> 6) * 32 * 4096;   // + kt*4096

    // consumer ldmatrix row/col within tiles
    const int a_row = lane & 15;
    const int a_co  = (lane >> 4) * 8;
    const int b_row = lane & 15;
    const int b_co  = (lane >> 4) * 8;

    float acc[2][4][4];
#pragma unroll
    for (int mi = 0; mi < 2; mi++)
#pragma unroll
        for (int jn = 0; jn < 4; jn++)
#pragma unroll
            for (int q = 0; q < 4; q++) acc[mi][jn][q] = 0.f;

    __syncthreads();   // coeff table ready

    // prologue: fill buffer 0 for kt=0
    {
        // B via cp.async
#pragma unroll
        for (int cc = 0; cc < 2; cc++) {
            int c = bc0 + cc;
            int kl = c >> 3, co = c & 7;
            uint32_t dst = smem_addr(Bs + kl * BNP + co * 8);
            CP_ASYNC16(dst, (const char*)(Bg) + (size_t)c * 16);
        }
        CP_COMMIT();
        // A: 4 coalesced x loads -> 4 evals
        float xv0 = xcol[0], xv1 = xcol[32], xv2 = xcol[64], xv3 = xcol[96];
        *(uint4*)&As[(r32 +  0) * AKP + chw * 8] = eval8(xv0, Ct);
        *(uint4*)&As[(r32 + 32) * AKP + chw * 8] = eval8(xv1, Ct);
        *(uint4*)&As[(r32 + 64) * AKP + chw * 8] = eval8(xv2, Ct);
        *(uint4*)&As[(r32 + 96) * AKP + chw * 8] = eval8(xv3, Ct);
        CP_WAIT0();
    }
    __syncthreads();

    const int NK = KTOT / BK;  // 32
    for (int kt = 0; kt < NK; kt++) {
        const int cur = kt & 1;
        const int nxt = cur ^ 1;
        float xv0, xv1, xv2, xv3;
        if (kt + 1 < NK) {
            // B for next chunk via cp.async into other buffer
            __half* Bn = Bs + nxt * (BK * BNP);
            const char* src = (const char*)(Bg + (size_t)(kt + 1) * 4096);
#pragma unroll
            for (int cc = 0; cc < 2; cc++) {
                int c = bc0 + cc;
                int kl = c >> 3, co = c & 7;
                CP_ASYNC16(smem_addr(Bn + kl * BNP + co * 8),
                           src + (size_t)c * 16);
            }
            CP_COMMIT();
            const float* xc = xcol + (size_t)(kt + 1) * 8 * MTOT;
            xv0 = xc[0]; xv1 = xc[32]; xv2 = xc[64]; xv3 = xc[96];
        }

        const __half* Asb = As + cur * (BM * AKP);
        const __half* Bsb = Bs + cur * (BK * BNP);
#pragma unroll
        for (int s = 0; s < 4; s++) {      // four k16 steps per BK=64
            uint32_t af[2][4], bf[2][4];
#pragma unroll
            for (int mi = 0; mi < 2; mi++)
                ldm_x4(af[mi], smem_addr(Asb + (wm + mi * 16 + a_row) * AKP
                                             + s * 16 + a_co));
#pragma unroll
            for (int j2 = 0; j2 < 2; j2++)
                ldm_x4t(bf[j2], smem_addr(Bsb + (s * 16 + b_row) * BNP
                                              + wn + j2 * 16 + b_co));
#pragma unroll
            for (int mi = 0; mi < 2; mi++)
#pragma unroll
                for (int j2 = 0; j2 < 2; j2++) {
                    mma16816(acc[mi][j2 * 2 + 0], af[mi], bf[j2][0], bf[j2][1]);
                    mma16816(acc[mi][j2 * 2 + 1], af[mi], bf[j2][2], bf[j2][3]);
                }
        }

        if (kt + 1 < NK) {
            __half* An = As + nxt * (BM * AKP);
            *(uint4*)&An[(r32 +  0) * AKP + chw * 8] = eval8(xv0, Ct);
            *(uint4*)&An[(r32 + 32) * AKP + chw * 8] = eval8(xv1, Ct);
            *(uint4*)&An[(r32 + 64) * AKP + chw * 8] = eval8(xv2, Ct);
            *(uint4*)&An[(r32 + 96) * AKP + chw * 8] = eval8(xv3, Ct);
            CP_WAIT0();
        }
        __syncthreads();
    }

    // epilogue
#pragma unroll
    for (int mi = 0; mi < 2; mi++) {
#pragma unroll
        for (int jn = 0; jn < 4; jn++) {
            int row = m0 + wm + mi * 16 + g;
            int col = n0 + wn + jn * 8 + c2;
            float2 v0 = make_float2(acc[mi][jn][0], acc[mi][jn][1]);
            float2 v1 = make_float2(acc[mi][jn][2], acc[mi][jn][3]);
            *(float2*)&C[(size_t)row * NTOT + col]       = v0;
            *(float2*)&C[(size_t)(row + 8) * NTOT + col] = v1;
        }
    }
}

// ---------------------------------------------------------------------------
extern "C" void kernel_launch(void* const* d_in, const int* in_sizes, int n_in,
                              void* d_out, int out_size) {
    (void)in_sizes; (void)n_in; (void)out_size;
    const float* x     = (const float*)d_in[0];   // (4,2048,256) f32
    const float* coeff = (const float*)d_in[1];   // (8,13) f32
    const float* gw    = (const float*)d_in[2];   // (256,256,8) f32
    float* out = (float*)d_out;                   // (4,2048,256) f32

    cudaFuncSetAttribute(fused_kernel,
                         cudaFuncAttributeMaxDynamicSharedMemorySize, SMEM_NEED);

    prep_kernel<<<256 + 2048, 256>>>(gw, x);
    dim3 grid(MTOT / BM, NTOT / BN);
    fused_kernel<<<grid, 256, SMEM_NEED>>>(coeff, out);
}

// round 7
// speedup vs baseline: 1.5222x; 1.3461x over previous
#include <cuda_runtime.h>
#include <cuda_fp16.h>
#include <cstdint>

// Problem constants
#define MTOT   8192          // B*S
#define IN_CH  256
#define NEXP   8
#define NBASIS 13
#define KTOT   2048          // IN_CH * NEXP
#define NTOT   256           // OUT

// Scratch (L2-resident between launches: 32MB + 1MB << 126MB L2)
__device__ __half g_A[(size_t)MTOT * KTOT];    // expert outputs [m][k], fp16
__device__ __half g_GB[(size_t)KTOT * NTOT];   // gates blocked:
// [nblk(4)][kt(32)][kl(64)][nl(64)] — each 64x64 tile contiguous (8KB)

// ---------------------------------------------------------------------------
// Prep kernel: blocks 0..255  -> softmax gates into blocked layout
//              blocks 256..   -> spline eval + expert combine into g_A
// ---------------------------------------------------------------------------
__global__ void prep_kernel(const float* __restrict__ gw,
                            const float* __restrict__ x,
                            const float* __restrict__ coeff) {
    if (blockIdx.x < 256) {
        int t = blockIdx.x * 256 + threadIdx.x;   // t = i*256 + o
        int o = t & 255;
        int i = t >> 8;
        const float4* g4 = (const float4*)(gw + (size_t)t * NEXP);
        float4 va = g4[0], vb = g4[1];
        float v[NEXP] = {va.x, va.y, va.z, va.w, vb.x, vb.y, vb.z, vb.w};
        float mx = v[0];
#pragma unroll
        for (int e = 1; e < NEXP; e++) mx = fmaxf(mx, v[e]);
        float s = 0.f;
#pragma unroll
        for (int e = 0; e < NEXP; e++) { v[e] = __expf(v[e] - mx); s += v[e]; }
        float inv = 1.0f / s;
        int nblk = o >> 6, nl = o & 63;
#pragma unroll
        for (int e = 0; e < NEXP; e++) {
            int k = i * NEXP + e;
            int kt = k >> 6, kl = k & 63;
            g_GB[(size_t)((nblk * 32 + kt) * 64 + kl) * 64 + nl] =
                __float2half(v[e] * inv);
        }
        return;
    }

    // ---- eval path ----
    __shared__ float4 Ct[NBASIS];   // 13 rows x 8 experts fp32? no: fp16 table
    __shared__ uint4  Cth[NBASIS];  // fp16 table rows (8 halves = 16B)
    int tid = threadIdx.x;
    if (tid < NBASIS * NEXP) {
        int e = tid & 7, n = tid >> 3;
        ((__half*)Cth)[n * 8 + e] = __float2half(coeff[e * NBASIS + n]);
    }
    __syncthreads();
    (void)Ct;

    int u = (blockIdx.x - 256) * 256 + tid;   // 0 .. 524287
    int m = u >> 6;
    int q = u & 63;                            // channel quad
    float4 xv = *(const float4*)(x + (size_t)m * IN_CH + q * 4);
    __half* dst = g_A + (size_t)m * KTOT + q * 32;

    float vals[4] = {xv.x, xv.y, xv.z, xv.w};
#pragma unroll
    for (int j = 0; j < 4; j++) {
        float xc = fminf(fmaxf(vals[j], -1.0f), 1.0f - 1e-6f);
        float uu = (xc + 1.0f) * 5.0f;
        int i0 = (int)uu;
        i0 = i0 > 9 ? 9 : (i0 < 0 ? 0 : i0);
        uu -= (float)i0;
        float om = 1.0f - uu;
        float u2 = uu * uu, u3 = u2 * uu;
        float b0 = om * om * om * (1.0f / 6.0f);
        float b1 = (3.0f * u3 - 6.0f * u2 + 4.0f) * (1.0f / 6.0f);
        float b2 = (-3.0f * u3 + 3.0f * u2 + 3.0f * uu + 1.0f) * (1.0f / 6.0f);
        float b3 = u3 * (1.0f / 6.0f);
        half2 w0 = __float2half2_rn(b0), w1 = __float2half2_rn(b1);
        half2 w2 = __float2half2_rn(b2), w3 = __float2half2_rn(b3);
        union { uint4 v; half2 h[4]; } c0, c1, c2, c3, out;
        c0.v = Cth[i0]; c1.v = Cth[i0 + 1]; c2.v = Cth[i0 + 2]; c3.v = Cth[i0 + 3];
#pragma unroll
        for (int p = 0; p < 4; p++) {
            half2 a = __hmul2(w0, c0.h[p]);
            a = __hfma2(w1, c1.h[p], a);
            a = __hfma2(w2, c2.h[p], a);
            out.h[p] = __hfma2(w3, c3.h[p], a);
        }
        *(uint4*)(dst + j * 8) = out.v;
    }
}

// ---------------------------------------------------------------------------
// Pure GEMM: C[m][o] = sum_k A[m][k] G[k][o].  M=8192 N=256 K=2048.
// BM=128 BN=64 BK=64, 4 warps each 32x64, 3-stage cp.async pipeline.
// ---------------------------------------------------------------------------
#define BM  128
#define BN  64
#define BK  64
#define NSTAGE 3
#define AKP 72    // A smem row stride (halves), conflict-free for ldmatrix
#define BNP 72
#define A_ST (BM * AKP * 2)              // 18432 B
#define B_ST (BK * BNP * 2)              // 9216 B
#define STG  (A_ST + B_ST)               // 27648 B per stage
#define SMEM_NEED (NSTAGE * STG)         // 82944 B

__device__ __forceinline__ uint32_t smem_addr(const void* p) {
    return (uint32_t)__cvta_generic_to_shared(p);
}

#define CP_ASYNC16(dst, src) \
    asm volatile("cp.async.cg.shared.global [%0], [%1], 16;" \
                 :: "r"(dst), "l"(src))
#define CP_COMMIT()  asm volatile("cp.async.commit_group;")
#define CP_WAIT(n)   asm volatile("cp.async.wait_group %0;" :: "n"(n) : "memory")

__device__ __forceinline__ void mma16816(float* d, const uint32_t* a,
                                         uint32_t b0, uint32_t b1) {
    asm volatile(
        "mma.sync.aligned.m16n8k16.row.col.f32.f16.f16.f32 "
        "{%0,%1,%2,%3}, {%4,%5,%6,%7}, {%8,%9}, {%0,%1,%2,%3};"
        : "+f"(d[0]), "+f"(d[1]), "+f"(d[2]), "+f"(d[3])
        : "r"(a[0]), "r"(a[1]), "r"(a[2]), "r"(a[3]), "r"(b0), "r"(b1));
}

__device__ __forceinline__ void ldm_x4(uint32_t* r, uint32_t ad) {
    asm volatile("ldmatrix.sync.aligned.m8n8.x4.shared.b16 {%0,%1,%2,%3}, [%4];"
                 : "=r"(r[0]), "=r"(r[1]), "=r"(r[2]), "=r"(r[3]) : "r"(ad));
}
__device__ __forceinline__ void ldm_x4t(uint32_t* r, uint32_t ad) {
    asm volatile("ldmatrix.sync.aligned.m8n8.x4.trans.shared.b16 {%0,%1,%2,%3}, [%4];"
                 : "=r"(r[0]), "=r"(r[1]), "=r"(r[2]), "=r"(r[3]) : "r"(ad));
}

__global__ void __launch_bounds__(128, 2)
gemm_kernel(float* __restrict__ C) {
    extern __shared__ char S[];

    const int tid  = threadIdx.x;
    const int lane = tid & 31;
    const int warp = tid >> 5;
    const int wm = warp * 32;          // 4 warps along M, each owns 32x64
    const int g  = lane >> 2;
    const int c2 = (lane & 3) * 2;

    const int m0 = blockIdx.x * BM;
    const int n0 = blockIdx.y * BN;

    const __half* Ag = g_A + (size_t)m0 * KTOT;
    const __half* Bg = g_GB + (size_t)(n0 >> 6) * 32 * 4096;  // per-kt 8KB tiles

    // loader mapping
    // A: 8 chunks of 16B per thread; chunk c = j*128 + tid: r=c>>3, co=c&7
    // B: 4 chunks; c = j*128 + tid: kl=c>>3, co=c&7 (tile contiguous)

    // consumer ldmatrix lane addressing
    const int lr = lane & 15;
    const int hc = (lane >> 4) * 8;

    float acc[2][8][4];
#pragma unroll
    for (int mi = 0; mi < 2; mi++)
#pragma unroll
        for (int jn = 0; jn < 8; jn++)
#pragma unroll
            for (int q = 0; q < 4; q++) acc[mi][jn][q] = 0.f;

    const int NK = KTOT / BK;   // 32

    // prologue: issue stages 0 and 1
#pragma unroll
    for (int st = 0; st < NSTAGE - 1; st++) {
        char* base = S + st * STG;
#pragma unroll
        for (int j = 0; j < 8; j++) {
            int c = j * 128 + tid;
            int r = c >> 3, co = c & 7;
            CP_ASYNC16(smem_addr(base + (r * AKP + co * 8) * 2),
                       Ag + (size_t)r * KTOT + st * BK + co * 8);
        }
#pragma unroll
        for (int j = 0; j < 4; j++) {
            int c = j * 128 + tid;
            CP_ASYNC16(smem_addr(base + A_ST + ((c >> 3) * BNP + (c & 7) * 8) * 2),
                       Bg + (size_t)st * 4096 + c * 8);
        }
        CP_COMMIT();
    }

    for (int kt = 0; kt < NK; kt++) {
        if (kt < NK - 1) { CP_WAIT(1); } else { CP_WAIT(0); }
        __syncthreads();

        // issue stage kt+2
        if (kt + 2 < NK) {
            char* base = S + ((kt + 2) % NSTAGE) * STG;
#pragma unroll
            for (int j = 0; j < 8; j++) {
                int c = j * 128 + tid;
                int r = c >> 3, co = c & 7;
                CP_ASYNC16(smem_addr(base + (r * AKP + co * 8) * 2),
                           Ag + (size_t)r * KTOT + (kt + 2) * BK + co * 8);
            }
#pragma unroll
            for (int j = 0; j < 4; j++) {
                int c = j * 128 + tid;
                CP_ASYNC16(smem_addr(base + A_ST +
                                     ((c >> 3) * BNP + (c & 7) * 8) * 2),
                           Bg + (size_t)(kt + 2) * 4096 + c * 8);
            }
            CP_COMMIT();
        }

        const __half* Asb = (const __half*)(S + (kt % NSTAGE) * STG);
        const __half* Bsb = (const __half*)(S + (kt % NSTAGE) * STG + A_ST);
#pragma unroll
        for (int s = 0; s < 4; s++) {
            uint32_t af[2][4], bf[4][4];
#pragma unroll
            for (int mi = 0; mi < 2; mi++)
                ldm_x4(af[mi], smem_addr(Asb + (wm + mi * 16 + lr) * AKP
                                             + s * 16 + hc));
#pragma unroll
            for (int j4 = 0; j4 < 4; j4++)
                ldm_x4t(bf[j4], smem_addr(Bsb + (s * 16 + lr) * BNP
                                              + j4 * 16 + hc));
#pragma unroll
            for (int mi = 0; mi < 2; mi++)
#pragma unroll
                for (int j4 = 0; j4 < 4; j4++) {
                    mma16816(acc[mi][2 * j4 + 0], af[mi], bf[j4][0], bf[j4][1]);
                    mma16816(acc[mi][2 * j4 + 1], af[mi], bf[j4][2], bf[j4][3]);
                }
        }
        __syncthreads();
    }

    // epilogue: warp owns rows [wm, wm+32) x all 64 cols
#pragma unroll
    for (int mi = 0; mi < 2; mi++) {
#pragma unroll
        for (int jn = 0; jn < 8; jn++) {
            int row = m0 + wm + mi * 16 + g;
            int col = n0 + jn * 8 + c2;
            float2 v0 = make_float2(acc[mi][jn][0], acc[mi][jn][1]);
            float2 v1 = make_float2(acc[mi][jn][2], acc[mi][jn][3]);
            *(float2*)&C[(size_t)row * NTOT + col]       = v0;
            *(float2*)&C[(size_t)(row + 8) * NTOT + col] = v1;
        }
    }
}

// ---------------------------------------------------------------------------
extern "C" void kernel_launch(void* const* d_in, const int* in_sizes, int n_in,
                              void* d_out, int out_size) {
    (void)in_sizes; (void)n_in; (void)out_size;
    const float* x     = (const float*)d_in[0];   // (4,2048,256) f32
    const float* coeff = (const float*)d_in[1];   // (8,13) f32
    const float* gw    = (const float*)d_in[2];   // (256,256,8) f32
    float* out = (float*)d_out;                   // (4,2048,256) f32

    cudaFuncSetAttribute(gemm_kernel,
                         cudaFuncAttributeMaxDynamicSharedMemorySize, SMEM_NEED);

    prep_kernel<<<256 + 2048, 256>>>(gw, x, coeff);
    dim3 grid(MTOT / BM, NTOT / BN);
    gemm_kernel<<<grid, 128, SMEM_NEED>>>(out);
}